// round 11
// baseline (speedup 1.0000x reference)
#include <cuda.h>
#include <cuda_runtime.h>
#include <cuda_fp16.h>
#include <cstdint>

// ---------------------------------------------------------------------------
// Shapes: tokens T = 4096, D = 1024, W = 4096, SLOT = 8, depth 3
// ---------------------------------------------------------------------------
#define NTOK  4096
#define NDIM  1024
#define NW    4096
#define NSLOT 8

typedef unsigned long long u64;
typedef unsigned int u32;

// Scratch (device globals: allocation-free)
__device__ __align__(1024) __half g_slotsH[NTOK * 16];          // [tok][16] fp16 A-operand
__device__ __align__(1024) u32    g_selH[1024 * 4 * 32 * 2];    // B-fragment order, 1 MB
__device__ __align__(1024) __half g_roots[(size_t)NTOK * NW];   // 32 MB fp16
__device__ __align__(1024) __half g_outwT[(size_t)NDIM * NW];   // 8 MB fp16 [n][k]

// ---------------------------------------------------------------------------
// helpers
// ---------------------------------------------------------------------------
__device__ __forceinline__ float ftanh(float x) {
    x = fminf(fmaxf(x, -15.f), 15.f);
    float e = __expf(2.f * x);
    return __fdividef(e - 1.f, e + 1.f);
}
__device__ __forceinline__ uint32_t s2u(const void* p) {
    uint32_t a;
    asm("{ .reg .u64 t; cvta.to.shared.u64 t, %1; cvt.u32.u64 %0, t; }" : "=r"(a) : "l"(p));
    return a;
}

// packed f32x2 ops
__device__ __forceinline__ u64 pk(float lo, float hi) {
    u64 r; asm("mov.b64 %0,{%1,%2};" : "=l"(r) : "f"(lo), "f"(hi)); return r;
}
__device__ __forceinline__ u64 pk1(float x) { return pk(x, x); }
__device__ __forceinline__ void upk(u64 v, float& lo, float& hi) {
    asm("mov.b64 {%0,%1},%2;" : "=f"(lo), "=f"(hi) : "l"(v));
}
__device__ __forceinline__ u64 f2fma(u64 a, u64 b, u64 c) {
    u64 d; asm("fma.rn.f32x2 %0,%1,%2,%3;" : "=l"(d) : "l"(a), "l"(b), "l"(c)); return d;
}
__device__ __forceinline__ u64 f2mul(u64 a, u64 b) {
    u64 d; asm("mul.rn.f32x2 %0,%1,%2;" : "=l"(d) : "l"(a), "l"(b)); return d;
}
// tree node on packed token-pair, single-instruction tanh
__device__ __forceinline__ u64 node2t(u64 l, u64 r, u64 LW, u64 RW, u64 PW,
                                      u64 DWP, u64 DWN, u64 NB) {
    u64 a = f2fma(LW, l, NB);
    a = f2fma(RW, r, a);
    a = f2fma(PW, f2mul(l, r), a);
    a = f2fma(DWP, l, a);
    a = f2fma(DWN, r, a);
    float x0, x1; upk(a, x0, x1);
    float t0, t1;
    asm("tanh.approx.f32 %0,%1;" : "=f"(t0) : "f"(x0));
    asm("tanh.approx.f32 %0,%1;" : "=f"(t1) : "f"(x1));
    return pk(t0, t1);
}

// ---------------------------------------------------------------------------
// Kernel A: slots = tanh(hidden @ slot_w + slot_b) -> fp16 [tok][16]
//   cols 0..7 = slots, col 8 = 1.0 (bias lane), cols 9..15 = 0
// ---------------------------------------------------------------------------
__global__ __launch_bounds__(256) void kA(const float* __restrict__ hidden,
                                          const float* __restrict__ sw,
                                          const float* __restrict__ sb,
                                          __half* __restrict__ slotsH) {
    const int wid = threadIdx.x >> 5, lane = threadIdx.x & 31;
    const int token = blockIdx.x * 8 + wid;
    const float* h = hidden + (size_t)token * NDIM;

    float acc[8] = {0, 0, 0, 0, 0, 0, 0, 0};
    for (int d0 = 0; d0 < NDIM; d0 += 128) {
        float4 hv = *(const float4*)(h + d0 + lane * 4);
        const float* hp = (const float*)&hv;
#pragma unroll
        for (int j = 0; j < 4; j++) {
            const float4* wr = (const float4*)(sw + (size_t)(d0 + lane * 4 + j) * NSLOT);
            float4 w0 = wr[0], w1 = wr[1];
            float hj = hp[j];
            acc[0] = fmaf(hj, w0.x, acc[0]); acc[1] = fmaf(hj, w0.y, acc[1]);
            acc[2] = fmaf(hj, w0.z, acc[2]); acc[3] = fmaf(hj, w0.w, acc[3]);
            acc[4] = fmaf(hj, w1.x, acc[4]); acc[5] = fmaf(hj, w1.y, acc[5]);
            acc[6] = fmaf(hj, w1.z, acc[6]); acc[7] = fmaf(hj, w1.w, acc[7]);
        }
    }
#pragma unroll
    for (int k = 0; k < 8; k++) {
        float v = acc[k];
#pragma unroll
        for (int off = 16; off; off >>= 1) v += __shfl_xor_sync(0xFFFFFFFFu, v, off);
        if (lane == k) slotsH[token * 16 + k] = __float2half_rn(ftanh(v + sb[k]));
    }
    if (lane >= 8 && lane < 16)
        slotsH[token * 16 + lane] = __float2half_rn(lane == 8 ? 1.f : 0.f);
}

// ---------------------------------------------------------------------------
// Kernel B: softmax fold -> selector in mma B-fragment order (fp16)
//   unit u = w>>2 covers 4 w; local col c = l*4 + (w&3); n-tile = c>>3
//   word index ((u*4+n)*32 + lane)*2 + j holds B[k0+8j .. +1][lane>>2],
//   k0 = (lane&3)*2 ; rows 0..7 = weights, 8 = bias, 9..15 = 0
// ---------------------------------------------------------------------------
__global__ __launch_bounds__(256) void kB(const float* __restrict__ logits,
                                          u32* __restrict__ selH) {
    const int idx = blockIdx.x * 256 + threadIdx.x;   // (w,l)
    const float* p = logits + (size_t)idx * 11;
    float x[11], mx = -1e30f;
#pragma unroll
    for (int c = 0; c < 11; c++) { x[c] = p[c]; mx = fmaxf(mx, x[c]); }
    float s = 0.f;
#pragma unroll
    for (int c = 0; c < 11; c++) { x[c] = __expf(x[c] - mx); s += x[c]; }
    const float inv = 1.0f / s;
    const int w = idx >> 3, l = idx & 7;
    const int u = w >> 2, wq = w & 3;
    const int c = l * 4 + wq, n = c >> 3, nc = c & 7;
    u32* base = selH + (size_t)(((u * 4 + n) * 32 + nc * 4) * 2);

#pragma unroll
    for (int i = 0; i < 4; i++) {
        u32 word;
        asm("cvt.rn.f16x2.f32 %0, %1, %2;" : "=r"(word)
            : "f"(x[2 * i + 1] * inv), "f"(x[2 * i] * inv));   // lo = x[2i]
        base[i * 2] = word;
    }
    u32 bw;
    asm("cvt.rn.f16x2.f32 %0, %1, %2;" : "=r"(bw)
        : "f"(0.f), "f"((x[10] - x[8]) * inv));                // lo = bias, hi = 0
    base[1] = bw;
    base[3] = 0; base[5] = 0; base[7] = 0;
}

// ---------------------------------------------------------------------------
// Kernel T: out_wT[n][k] = fp16(out_w[k][n])
// ---------------------------------------------------------------------------
__global__ __launch_bounds__(256) void kT(const float* __restrict__ w,
                                          __half* __restrict__ wt) {
    __shared__ float t[32][33];
    const int n0 = blockIdx.x * 32, k0 = blockIdx.y * 32;
#pragma unroll
    for (int j = 0; j < 4; j++)
        t[threadIdx.y + j * 8][threadIdx.x] =
            w[(size_t)(k0 + threadIdx.y + j * 8) * NDIM + n0 + threadIdx.x];
    __syncthreads();
#pragma unroll
    for (int j = 0; j < 4; j++)
        wt[(size_t)(n0 + threadIdx.y + j * 8) * NW + k0 + threadIdx.x] =
            __float2half_rn(t[threadIdx.x][threadIdx.y + j * 8]);
}

// ---------------------------------------------------------------------------
// Kernel C: leaf einsum on HMMA (m16n8k16, K=16 one-shot) + register tree
//   warp owns unit u (4 w, 32 (w,l) cols); B-frags loop-invariant in regs.
//   After shfl_xor(2): thread holds 8 leaves of 1 w for 2 tokens (packed).
// ---------------------------------------------------------------------------
__global__ __launch_bounds__(128) void kC(const float* __restrict__ np,
                                          const u32* __restrict__ selH,
                                          const u32* __restrict__ slotsH,
                                          __half* __restrict__ roots) {
    const int wid = threadIdx.x >> 5, lane = threadIdx.x & 31;
    const int u = blockIdx.x * 4 + wid;
    const int wbase = u * 4;
    const int t = lane & 3, q = lane >> 2;

    u32 bf[4][2];
#pragma unroll
    for (int n = 0; n < 4; n++) {
        const u32* p = selH + (size_t)(((u * 4 + n) * 32 + lane) * 2);
        bf[n][0] = p[0]; bf[n][1] = p[1];
    }
    const u64 LW = pk1(np[0]), RW = pk1(np[1]), PW = pk1(np[2]);
    const u64 DWP = pk1(np[3]), DWN = pk1(-np[3]), NB = pk1(np[4]);

    const int oc = t >> 1;          // own col-bit = assigned wq's column
    const bool evenl = (t < 2);     // own values are even leaves?

    const int tu0 = blockIdx.y * 64;
    for (int tu = 0; tu < 64; tu++) {
        const int tok = (tu0 + tu) * 16;
        const u32* ar = slotsH + (size_t)(tok + q) * 8;
        u32 a0 = ar[t], a2 = ar[t + 4];
        u32 a1 = ar[64 + t], a3 = ar[64 + t + 4];   // rows +8

        float z = 0.f;
        float acc[4][4];
#pragma unroll
        for (int n = 0; n < 4; n++)
            asm volatile(
                "mma.sync.aligned.m16n8k16.row.col.f32.f16.f16.f32 "
                "{%0,%1,%2,%3}, {%4,%5,%6,%7}, {%8,%9}, {%10,%10,%10,%10};"
                : "=f"(acc[n][0]), "=f"(acc[n][1]), "=f"(acc[n][2]), "=f"(acc[n][3])
                : "r"(a0), "r"(a1), "r"(a2), "r"(a3),
                  "r"(bf[n][0]), "r"(bf[n][1]), "f"(z));

        // keep own-wq column, exchange the other with partner lane (xor 2)
        u64 K[4], R[4];
#pragma unroll
        for (int n = 0; n < 4; n++) {
            K[n] = pk(acc[n][oc], acc[n][oc + 2]);
            u64 S = pk(acc[n][oc ^ 1], acc[n][(oc ^ 1) + 2]);
            R[n] = __shfl_xor_sync(0xFFFFFFFFu, S, 2);
        }
        // tree (packed over 2 tokens)
        u64 N1[4];
#pragma unroll
        for (int i = 0; i < 4; i++) {
            u64 E = evenl ? K[i] : R[i];
            u64 O = evenl ? R[i] : K[i];
            N1[i] = node2t(E, O, LW, RW, PW, DWP, DWN, NB);
        }
        u64 M0 = node2t(N1[0], N1[1], LW, RW, PW, DWP, DWN, NB);
        u64 M1 = node2t(N1[2], N1[3], LW, RW, PW, DWP, DWN, NB);
        u64 RT = node2t(M0, M1, LW, RW, PW, DWP, DWN, NB);

        float r0, r1; upk(RT, r0, r1);
        u32 val;
        asm("cvt.rn.f16x2.f32 %0, %1, %2;" : "=r"(val) : "f"(r1), "f"(r0));

        // quad combine: w order wq 0,1,2,3 <- quad lanes {0,2,1,3}
        u32 v1 = __shfl_sync(0xFFFFFFFFu, val, 2, 4);
        u32 v2 = __shfl_sync(0xFFFFFFFFu, val, 1, 4);
        u32 v3 = __shfl_sync(0xFFFFFFFFu, val, 3, 4);
        if (t == 0) {
            u32 w0 = __byte_perm(val, v1, 0x5410);
            u32 w1 = __byte_perm(v2, v3, 0x5410);
            u32 x0 = __byte_perm(val, v1, 0x7632);
            u32 x1 = __byte_perm(v2, v3, 0x7632);
            *(uint2*)(roots + (size_t)(tok + q) * NW + wbase) = make_uint2(w0, w1);
            *(uint2*)(roots + (size_t)(tok + q + 8) * NW + wbase) = make_uint2(x0, x1);
        }
    }
}

// ---------------------------------------------------------------------------
// Kernel D (unchanged): out = roots @ out_wT^T + out_b, fp16 HMMA m16n8k16
// ---------------------------------------------------------------------------
#define KD_ITERS (NW / 32)
#define KD_STAGE 16384

__device__ __forceinline__ void cpa16(uint32_t dst, const void* src) {
    asm volatile("cp.async.cg.shared.global [%0], [%1], 16;" :: "r"(dst), "l"(src) : "memory");
}

__global__ __launch_bounds__(256, 2) void kD(const __half* __restrict__ A,
                                             const __half* __restrict__ B,
                                             const float* __restrict__ bias,
                                             float* __restrict__ C) {
    __shared__ __align__(128) char smem[3 * KD_STAGE];
    const uint32_t sb = s2u(smem);
    const int tid = threadIdx.x, wid = tid >> 5, lane = tid & 31;
    const int bm = blockIdx.y, bn = blockIdx.x;
    const int warp_m = wid >> 2, warp_n = wid & 3;

    const int r0 = tid >> 2, c0 = tid & 3, r1 = r0 + 64;
    const uint32_t sA0 = r0 * 64 + ((c0 ^ ((r0 >> 1) & 3)) << 4);
    const uint32_t sA1 = r1 * 64 + ((c0 ^ ((r1 >> 1) & 3)) << 4);
    const __half* gA0 = A + (size_t)(bm * 128 + r0) * NW + c0 * 8;
    const __half* gA1 = A + (size_t)(bm * 128 + r1) * NW + c0 * 8;
    const __half* gB0 = B + (size_t)(bn * 128 + r0) * NW + c0 * 8;
    const __half* gB1 = B + (size_t)(bn * 128 + r1) * NW + c0 * 8;

    const int mat = lane >> 3, lrow = lane & 7;
    uint32_t adA[4][2], adB[2][2];
#pragma unroll
    for (int mi = 0; mi < 4; mi++) {
        int row = warp_m * 64 + mi * 16 + (mat & 1) * 8 + lrow;
        int coff = mat >> 1, sw = (row >> 1) & 3;
#pragma unroll
        for (int ks = 0; ks < 2; ks++)
            adA[mi][ks] = row * 64 + (((ks * 2 + coff) ^ sw) << 4);
    }
#pragma unroll
    for (int p = 0; p < 2; p++) {
        int nrow = warp_n * 32 + p * 16 + (mat >> 1) * 8 + lrow;
        int coff = mat & 1, sw = (nrow >> 1) & 3;
#pragma unroll
        for (int ks = 0; ks < 2; ks++)
            adB[p][ks] = 8192 + nrow * 64 + (((ks * 2 + coff) ^ sw) << 4);
    }

    float acc[4][4][4];
#pragma unroll
    for (int i = 0; i < 4; i++)
#pragma unroll
        for (int j = 0; j < 4; j++)
#pragma unroll
            for (int k = 0; k < 4; k++) acc[i][j][k] = 0.f;

#pragma unroll
    for (int s = 0; s < 2; s++) {
        uint32_t b = sb + s * KD_STAGE;
        cpa16(b + sA0, gA0 + s * 32);
        cpa16(b + sA1, gA1 + s * 32);
        cpa16(b + 8192 + sA0, gB0 + s * 32);
        cpa16(b + 8192 + sA1, gB1 + s * 32);
        asm volatile("cp.async.commit_group;" ::: "memory");
    }

    for (int k = 0; k < KD_ITERS; k++) {
        asm volatile("cp.async.wait_group 1;" ::: "memory");
        __syncthreads();
        const int s = k % 3;
        if (k + 2 < KD_ITERS) {
            const int sn = (k + 2) % 3;
            uint32_t b = sb + sn * KD_STAGE;
            cpa16(b + sA0, gA0 + (k + 2) * 32);
            cpa16(b + sA1, gA1 + (k + 2) * 32);
            cpa16(b + 8192 + sA0, gB0 + (k + 2) * 32);
            cpa16(b + 8192 + sA1, gB1 + (k + 2) * 32);
        }
        asm volatile("cp.async.commit_group;" ::: "memory");

        const uint32_t base = sb + s * KD_STAGE;
#pragma unroll
        for (int ks = 0; ks < 2; ks++) {
            uint32_t af[4][4], bfr[4][2];
#pragma unroll
            for (int mi = 0; mi < 4; mi++)
                asm volatile(
                    "ldmatrix.sync.aligned.m8n8.x4.shared.b16 {%0,%1,%2,%3}, [%4];"
                    : "=r"(af[mi][0]), "=r"(af[mi][1]), "=r"(af[mi][2]), "=r"(af[mi][3])
                    : "r"(base + adA[mi][ks]));
#pragma unroll
            for (int p = 0; p < 2; p++)
                asm volatile(
                    "ldmatrix.sync.aligned.m8n8.x4.shared.b16 {%0,%1,%2,%3}, [%4];"
                    : "=r"(bfr[2 * p][0]), "=r"(bfr[2 * p][1]),
                      "=r"(bfr[2 * p + 1][0]), "=r"(bfr[2 * p + 1][1])
                    : "r"(base + adB[p][ks]));
#pragma unroll
            for (int mi = 0; mi < 4; mi++)
#pragma unroll
                for (int ni = 0; ni < 4; ni++)
                    asm volatile(
                        "mma.sync.aligned.m16n8k16.row.col.f32.f16.f16.f32 "
                        "{%0,%1,%2,%3}, {%4,%5,%6,%7}, {%8,%9}, {%0,%1,%2,%3};"
                        : "+f"(acc[mi][ni][0]), "+f"(acc[mi][ni][1]),
                          "+f"(acc[mi][ni][2]), "+f"(acc[mi][ni][3])
                        : "r"(af[mi][0]), "r"(af[mi][1]), "r"(af[mi][2]), "r"(af[mi][3]),
                          "r"(bfr[ni][0]), "r"(bfr[ni][1]));
        }
    }

    const int gm0 = bm * 128 + warp_m * 64 + (lane >> 2);
#pragma unroll
    for (int mi = 0; mi < 4; mi++) {
#pragma unroll
        for (int ni = 0; ni < 4; ni++) {
            int col = bn * 128 + warp_n * 32 + ni * 8 + (lane & 3) * 2;
            float b0 = __ldg(bias + col), b1 = __ldg(bias + col + 1);
            int r = gm0 + mi * 16;
            float2 v0 = make_float2(acc[mi][ni][0] + b0, acc[mi][ni][1] + b1);
            float2 v1 = make_float2(acc[mi][ni][2] + b0, acc[mi][ni][3] + b1);
            *(float2*)(C + (size_t)r * NDIM + col) = v0;
            *(float2*)(C + (size_t)(r + 8) * NDIM + col) = v1;
        }
    }
}

// ---------------------------------------------------------------------------
// launch
// inputs: 0 hidden, 1 slot_w, 2 slot_b, 3 leaf_logits, 4 node_params,
//         5 out_w, 6 out_b ; output float32 [4096,1024]
// ---------------------------------------------------------------------------
extern "C" void kernel_launch(void* const* d_in, const int* in_sizes, int n_in,
                              void* d_out, int out_size) {
    const float* hidden      = (const float*)d_in[0];
    const float* slot_w      = (const float*)d_in[1];
    const float* slot_b      = (const float*)d_in[2];
    const float* leaf_logits = (const float*)d_in[3];
    const float* node_params = (const float*)d_in[4];
    const float* out_w       = (const float*)d_in[5];
    const float* out_b       = (const float*)d_in[6];
    float* out = (float*)d_out;

    __half* slotsH; cudaGetSymbolAddress((void**)&slotsH, g_slotsH);
    u32*    selH;   cudaGetSymbolAddress((void**)&selH,   g_selH);
    __half* roots;  cudaGetSymbolAddress((void**)&roots,  g_roots);
    __half* outwT;  cudaGetSymbolAddress((void**)&outwT,  g_outwT);

    kA<<<NTOK / 8, 256>>>(hidden, slot_w, slot_b, slotsH);
    kB<<<(NW * 8) / 256, 256>>>(leaf_logits, selH);
    dim3 gt(NDIM / 32, NW / 32);
    kT<<<gt, dim3(32, 8)>>>(out_w, outwT);
    dim3 gc(NW / 16, 4);   // 256 w-units x 4 token-quarters
    kC<<<gc, 128>>>(node_params, selH, (const u32*)slotsH, roots);
    dim3 gd(NDIM / 128, NTOK / 128);
    kD<<<gd, 256>>>(roots, outwT, out_b, out);
}

// round 13
// speedup vs baseline: 1.5505x; 1.5505x over previous
#include <cuda.h>
#include <cuda_runtime.h>
#include <cuda_fp16.h>
#include <cstdint>

// ---------------------------------------------------------------------------
// Shapes: tokens T = 4096, D = 1024, W = 4096, SLOT = 8, depth 3
// ---------------------------------------------------------------------------
#define NTOK  4096
#define NDIM  1024
#define NW    4096
#define NSLOT 8

typedef unsigned long long u64;
typedef unsigned int u32;

// Scratch (device globals: allocation-free)
__device__ __align__(1024) __half g_slotsH[NTOK * 16];          // [tok][16] fp16 A-operand
__device__ __align__(1024) u32    g_selH[1024 * 4 * 32 * 2];    // B-fragment order, 1 MB
__device__ __align__(1024) __half g_roots[(size_t)NTOK * NW];   // 32 MB fp16
__device__ __align__(1024) __half g_outwT[(size_t)NDIM * NW];   // 8 MB fp16 [n][k]

// ---------------------------------------------------------------------------
// helpers
// ---------------------------------------------------------------------------
__device__ __forceinline__ float ftanh(float x) {
    x = fminf(fmaxf(x, -15.f), 15.f);
    float e = __expf(2.f * x);
    return __fdividef(e - 1.f, e + 1.f);
}
__device__ __forceinline__ uint32_t s2u(const void* p) {
    uint32_t a;
    asm("{ .reg .u64 t; cvta.to.shared.u64 t, %1; cvt.u32.u64 %0, t; }" : "=r"(a) : "l"(p));
    return a;
}

// packed f32x2 ops
__device__ __forceinline__ u64 pk(float lo, float hi) {
    u64 r; asm("mov.b64 %0,{%1,%2};" : "=l"(r) : "f"(lo), "f"(hi)); return r;
}
__device__ __forceinline__ u64 pk1(float x) { return pk(x, x); }
__device__ __forceinline__ void upk(u64 v, float& lo, float& hi) {
    asm("mov.b64 {%0,%1},%2;" : "=f"(lo), "=f"(hi) : "l"(v));
}
__device__ __forceinline__ u64 f2fma(u64 a, u64 b, u64 c) {
    u64 d; asm("fma.rn.f32x2 %0,%1,%2,%3;" : "=l"(d) : "l"(a), "l"(b), "l"(c)); return d;
}
__device__ __forceinline__ u64 f2mul(u64 a, u64 b) {
    u64 d; asm("mul.rn.f32x2 %0,%1,%2;" : "=l"(d) : "l"(a), "l"(b)); return d;
}
// tree node on packed token-pair, single-instruction tanh
__device__ __forceinline__ u64 node2t(u64 l, u64 r, u64 LW, u64 RW, u64 PW,
                                      u64 DWP, u64 DWN, u64 NB) {
    u64 a = f2fma(LW, l, NB);
    a = f2fma(RW, r, a);
    a = f2fma(PW, f2mul(l, r), a);
    a = f2fma(DWP, l, a);
    a = f2fma(DWN, r, a);
    float x0, x1; upk(a, x0, x1);
    float t0, t1;
    asm("tanh.approx.f32 %0,%1;" : "=f"(t0) : "f"(x0));
    asm("tanh.approx.f32 %0,%1;" : "=f"(t1) : "f"(x1));
    return pk(t0, t1);
}

// ---------------------------------------------------------------------------
// Kernel A: slots = tanh(hidden @ slot_w + slot_b) -> fp16 [tok][16]
//   cols 0..7 = slots, col 8 = 1.0 (bias lane), cols 9..15 = 0
// ---------------------------------------------------------------------------
__global__ __launch_bounds__(256) void kA(const float* __restrict__ hidden,
                                          const float* __restrict__ sw,
                                          const float* __restrict__ sb,
                                          __half* __restrict__ slotsH) {
    const int wid = threadIdx.x >> 5, lane = threadIdx.x & 31;
    const int token = blockIdx.x * 8 + wid;
    const float* h = hidden + (size_t)token * NDIM;

    float acc[8] = {0, 0, 0, 0, 0, 0, 0, 0};
    for (int d0 = 0; d0 < NDIM; d0 += 128) {
        float4 hv = *(const float4*)(h + d0 + lane * 4);
        const float* hp = (const float*)&hv;
#pragma unroll
        for (int j = 0; j < 4; j++) {
            const float4* wr = (const float4*)(sw + (size_t)(d0 + lane * 4 + j) * NSLOT);
            float4 w0 = wr[0], w1 = wr[1];
            float hj = hp[j];
            acc[0] = fmaf(hj, w0.x, acc[0]); acc[1] = fmaf(hj, w0.y, acc[1]);
            acc[2] = fmaf(hj, w0.z, acc[2]); acc[3] = fmaf(hj, w0.w, acc[3]);
            acc[4] = fmaf(hj, w1.x, acc[4]); acc[5] = fmaf(hj, w1.y, acc[5]);
            acc[6] = fmaf(hj, w1.z, acc[6]); acc[7] = fmaf(hj, w1.w, acc[7]);
        }
    }
#pragma unroll
    for (int k = 0; k < 8; k++) {
        float v = acc[k];
#pragma unroll
        for (int off = 16; off; off >>= 1) v += __shfl_xor_sync(0xFFFFFFFFu, v, off);
        if (lane == k) slotsH[token * 16 + k] = __float2half_rn(ftanh(v + sb[k]));
    }
    if (lane >= 8 && lane < 16)
        slotsH[token * 16 + lane] = __float2half_rn(lane == 8 ? 1.f : 0.f);
}

// ---------------------------------------------------------------------------
// Kernel B: softmax fold -> selector in mma B-fragment order (fp16)
// ---------------------------------------------------------------------------
__global__ __launch_bounds__(256) void kB(const float* __restrict__ logits,
                                          u32* __restrict__ selH) {
    const int idx = blockIdx.x * 256 + threadIdx.x;   // (w,l)
    const float* p = logits + (size_t)idx * 11;
    float x[11], mx = -1e30f;
#pragma unroll
    for (int c = 0; c < 11; c++) { x[c] = p[c]; mx = fmaxf(mx, x[c]); }
    float s = 0.f;
#pragma unroll
    for (int c = 0; c < 11; c++) { x[c] = __expf(x[c] - mx); s += x[c]; }
    const float inv = 1.0f / s;
    const int w = idx >> 3, l = idx & 7;
    const int u = w >> 2, wq = w & 3;
    const int c = l * 4 + wq, n = c >> 3, nc = c & 7;
    u32* base = selH + (size_t)(((u * 4 + n) * 32 + nc * 4) * 2);

#pragma unroll
    for (int i = 0; i < 4; i++) {
        u32 word;
        asm("cvt.rn.f16x2.f32 %0, %1, %2;" : "=r"(word)
            : "f"(x[2 * i + 1] * inv), "f"(x[2 * i] * inv));   // lo = x[2i]
        base[i * 2] = word;
    }
    u32 bw;
    asm("cvt.rn.f16x2.f32 %0, %1, %2;" : "=r"(bw)
        : "f"(0.f), "f"((x[10] - x[8]) * inv));                // lo = bias, hi = 0
    base[1] = bw;
    base[3] = 0; base[5] = 0; base[7] = 0;
}

// ---------------------------------------------------------------------------
// Kernel T: out_wT[n][k] = fp16(out_w[k][n])
// ---------------------------------------------------------------------------
__global__ __launch_bounds__(256) void kT(const float* __restrict__ w,
                                          __half* __restrict__ wt) {
    __shared__ float t[32][33];
    const int n0 = blockIdx.x * 32, k0 = blockIdx.y * 32;
#pragma unroll
    for (int j = 0; j < 4; j++)
        t[threadIdx.y + j * 8][threadIdx.x] =
            w[(size_t)(k0 + threadIdx.y + j * 8) * NDIM + n0 + threadIdx.x];
    __syncthreads();
#pragma unroll
    for (int j = 0; j < 4; j++)
        wt[(size_t)(n0 + threadIdx.y + j * 8) * NW + k0 + threadIdx.x] =
            __float2half_rn(t[threadIdx.x][threadIdx.y + j * 8]);
}

// ---------------------------------------------------------------------------
// Kernel C: leaf einsum on HMMA + register tree.
//   Block = 8 warps = 32 w, 512 tokens. Slots staged in smem (48B row pad,
//   conflict-free LDSM); roots staged in smem tile -> coalesced 64B stores.
// ---------------------------------------------------------------------------
#define KC_TPB 512

__global__ __launch_bounds__(256) void kC(const float* __restrict__ np,
                                          const u32* __restrict__ selH,
                                          const u32* __restrict__ slotsH,
                                          __half* __restrict__ roots) {
    __shared__ __align__(16) char ssl[KC_TPB * 48];      // 24 KB slot tile
    __shared__ __align__(16) char sroot[2][16 * 72];     // double-buffered out tile
    const int tid = threadIdx.x, wid = tid >> 5, lane = tid & 31;
    const int u = blockIdx.x * 8 + wid;
    const int wblk = blockIdx.x * 32;
    const int t = lane & 3, q = lane >> 2;
    const int tok0 = blockIdx.y * KC_TPB;

    // stage slots: 1024 chunks of 16B, fully coalesced gmem reads
    const uint4* gsl = ((const uint4*)slotsH) + tok0 * 2;
    for (int c = tid; c < KC_TPB * 2; c += 256) {
        uint4 v = gsl[c];
        *(uint4*)(ssl + (c >> 1) * 48 + (c & 1) * 16) = v;
    }

    // loop-invariant B-fragments (selector)
    u32 bf[4][2];
#pragma unroll
    for (int n = 0; n < 4; n++) {
        const u32* p = selH + (size_t)(((u * 4 + n) * 32 + lane) * 2);
        bf[n][0] = p[0]; bf[n][1] = p[1];
    }
    const u64 LW = pk1(np[0]), RW = pk1(np[1]), PW = pk1(np[2]);
    const u64 DWP = pk1(np[3]), DWN = pk1(-np[3]), NB = pk1(np[4]);

    const int oc = t >> 1;
    const bool evenl = (t < 2);
    const int mat = lane >> 3, lrow = lane & 7;
    const uint32_t sbase = s2u(ssl) + ((mat & 1) * 8 + lrow) * 48 + (mat >> 1) * 16;
    __syncthreads();

    for (int tu = 0; tu < KC_TPB / 16; tu++) {
        const int tl = tu * 16;
        u32 a0, a1, a2, a3;
        asm volatile(
            "ldmatrix.sync.aligned.m8n8.x4.shared.b16 {%0,%1,%2,%3}, [%4];"
            : "=r"(a0), "=r"(a1), "=r"(a2), "=r"(a3)
            : "r"(sbase + tl * 48));

        float z = 0.f;
        float acc[4][4];
#pragma unroll
        for (int n = 0; n < 4; n++)
            asm volatile(
                "mma.sync.aligned.m16n8k16.row.col.f32.f16.f16.f32 "
                "{%0,%1,%2,%3}, {%4,%5,%6,%7}, {%8,%9}, {%10,%10,%10,%10};"
                : "=f"(acc[n][0]), "=f"(acc[n][1]), "=f"(acc[n][2]), "=f"(acc[n][3])
                : "r"(a0), "r"(a1), "r"(a2), "r"(a3),
                  "r"(bf[n][0]), "r"(bf[n][1]), "f"(z));

        // keep own-wq column, exchange the other with partner lane (xor 2)
        u64 K[4], R[4];
#pragma unroll
        for (int n = 0; n < 4; n++) {
            K[n] = pk(acc[n][oc], acc[n][oc + 2]);
            u64 S = pk(acc[n][oc ^ 1], acc[n][(oc ^ 1) + 2]);
            R[n] = __shfl_xor_sync(0xFFFFFFFFu, S, 2);
        }
        u64 N1[4];
#pragma unroll
        for (int i = 0; i < 4; i++) {
            u64 E = evenl ? K[i] : R[i];
            u64 O = evenl ? R[i] : K[i];
            N1[i] = node2t(E, O, LW, RW, PW, DWP, DWN, NB);
        }
        u64 M0 = node2t(N1[0], N1[1], LW, RW, PW, DWP, DWN, NB);
        u64 M1 = node2t(N1[2], N1[3], LW, RW, PW, DWP, DWN, NB);
        u64 RT = node2t(M0, M1, LW, RW, PW, DWP, DWN, NB);

        float r0, r1; upk(RT, r0, r1);
        u32 val;
        asm("cvt.rn.f16x2.f32 %0, %1, %2;" : "=r"(val) : "f"(r1), "f"(r0));

        // quad combine: w order wq 0,1,2,3 <- quad lanes {0,2,1,3}
        u32 v1 = __shfl_sync(0xFFFFFFFFu, val, 2, 4);
        u32 v2 = __shfl_sync(0xFFFFFFFFu, val, 1, 4);
        u32 v3 = __shfl_sync(0xFFFFFFFFu, val, 3, 4);
        char* sr = sroot[tu & 1];
        if (t == 0) {
            u32 w0 = __byte_perm(val, v1, 0x5410);
            u32 w1 = __byte_perm(v2, v3, 0x5410);
            u32 x0 = __byte_perm(val, v1, 0x7632);
            u32 x1 = __byte_perm(v2, v3, 0x7632);
            *(uint2*)(sr + q * 72 + wid * 8) = make_uint2(w0, w1);
            *(uint2*)(sr + (q + 8) * 72 + wid * 8) = make_uint2(x0, x1);
        }
        __syncthreads();
        // coalesced copy-out: 16 rows x 64B
        const int r = tid >> 4, cb = (tid & 15) * 4;
        u32 v = *(const u32*)(sr + r * 72 + cb);
        *(u32*)((char*)(roots + (size_t)(tok0 + tl + r) * NW + wblk) + cb) = v;
    }
}

// ---------------------------------------------------------------------------
// Kernel D (unchanged): out = roots @ out_wT^T + out_b, fp16 HMMA m16n8k16
// ---------------------------------------------------------------------------
#define KD_ITERS (NW / 32)
#define KD_STAGE 16384

__device__ __forceinline__ void cpa16(uint32_t dst, const void* src) {
    asm volatile("cp.async.cg.shared.global [%0], [%1], 16;" :: "r"(dst), "l"(src) : "memory");
}

__global__ __launch_bounds__(256, 2) void kD(const __half* __restrict__ A,
                                             const __half* __restrict__ B,
                                             const float* __restrict__ bias,
                                             float* __restrict__ C) {
    __shared__ __align__(128) char smem[3 * KD_STAGE];
    const uint32_t sb = s2u(smem);
    const int tid = threadIdx.x, wid = tid >> 5, lane = tid & 31;
    const int bm = blockIdx.y, bn = blockIdx.x;
    const int warp_m = wid >> 2, warp_n = wid & 3;

    const int r0 = tid >> 2, c0 = tid & 3, r1 = r0 + 64;
    const uint32_t sA0 = r0 * 64 + ((c0 ^ ((r0 >> 1) & 3)) << 4);
    const uint32_t sA1 = r1 * 64 + ((c0 ^ ((r1 >> 1) & 3)) << 4);
    const __half* gA0 = A + (size_t)(bm * 128 + r0) * NW + c0 * 8;
    const __half* gA1 = A + (size_t)(bm * 128 + r1) * NW + c0 * 8;
    const __half* gB0 = B + (size_t)(bn * 128 + r0) * NW + c0 * 8;
    const __half* gB1 = B + (size_t)(bn * 128 + r1) * NW + c0 * 8;

    const int mat = lane >> 3, lrow = lane & 7;
    uint32_t adA[4][2], adB[2][2];
#pragma unroll
    for (int mi = 0; mi < 4; mi++) {
        int row = warp_m * 64 + mi * 16 + (mat & 1) * 8 + lrow;
        int coff = mat >> 1, sw = (row >> 1) & 3;
#pragma unroll
        for (int ks = 0; ks < 2; ks++)
            adA[mi][ks] = row * 64 + (((ks * 2 + coff) ^ sw) << 4);
    }
#pragma unroll
    for (int p = 0; p < 2; p++) {
        int nrow = warp_n * 32 + p * 16 + (mat >> 1) * 8 + lrow;
        int coff = mat & 1, sw = (nrow >> 1) & 3;
#pragma unroll
        for (int ks = 0; ks < 2; ks++)
            adB[p][ks] = 8192 + nrow * 64 + (((ks * 2 + coff) ^ sw) << 4);
    }

    float acc[4][4][4];
#pragma unroll
    for (int i = 0; i < 4; i++)
#pragma unroll
        for (int j = 0; j < 4; j++)
#pragma unroll
            for (int k = 0; k < 4; k++) acc[i][j][k] = 0.f;

#pragma unroll
    for (int s = 0; s < 2; s++) {
        uint32_t b = sb + s * KD_STAGE;
        cpa16(b + sA0, gA0 + s * 32);
        cpa16(b + sA1, gA1 + s * 32);
        cpa16(b + 8192 + sA0, gB0 + s * 32);
        cpa16(b + 8192 + sA1, gB1 + s * 32);
        asm volatile("cp.async.commit_group;" ::: "memory");
    }

    for (int k = 0; k < KD_ITERS; k++) {
        asm volatile("cp.async.wait_group 1;" ::: "memory");
        __syncthreads();
        const int s = k % 3;
        if (k + 2 < KD_ITERS) {
            const int sn = (k + 2) % 3;
            uint32_t b = sb + sn * KD_STAGE;
            cpa16(b + sA0, gA0 + (k + 2) * 32);
            cpa16(b + sA1, gA1 + (k + 2) * 32);
            cpa16(b + 8192 + sA0, gB0 + (k + 2) * 32);
            cpa16(b + 8192 + sA1, gB1 + (k + 2) * 32);
        }
        asm volatile("cp.async.commit_group;" ::: "memory");

        const uint32_t base = sb + s * KD_STAGE;
#pragma unroll
        for (int ks = 0; ks < 2; ks++) {
            uint32_t af[4][4], bfr[4][2];
#pragma unroll
            for (int mi = 0; mi < 4; mi++)
                asm volatile(
                    "ldmatrix.sync.aligned.m8n8.x4.shared.b16 {%0,%1,%2,%3}, [%4];"
                    : "=r"(af[mi][0]), "=r"(af[mi][1]), "=r"(af[mi][2]), "=r"(af[mi][3])
                    : "r"(base + adA[mi][ks]));
#pragma unroll
            for (int p = 0; p < 2; p++)
                asm volatile(
                    "ldmatrix.sync.aligned.m8n8.x4.shared.b16 {%0,%1,%2,%3}, [%4];"
                    : "=r"(bfr[2 * p][0]), "=r"(bfr[2 * p][1]),
                      "=r"(bfr[2 * p + 1][0]), "=r"(bfr[2 * p + 1][1])
                    : "r"(base + adB[p][ks]));
#pragma unroll
            for (int mi = 0; mi < 4; mi++)
#pragma unroll
                for (int ni = 0; ni < 4; ni++)
                    asm volatile(
                        "mma.sync.aligned.m16n8k16.row.col.f32.f16.f16.f32 "
                        "{%0,%1,%2,%3}, {%4,%5,%6,%7}, {%8,%9}, {%0,%1,%2,%3};"
                        : "+f"(acc[mi][ni][0]), "+f"(acc[mi][ni][1]),
                          "+f"(acc[mi][ni][2]), "+f"(acc[mi][ni][3])
                        : "r"(af[mi][0]), "r"(af[mi][1]), "r"(af[mi][2]), "r"(af[mi][3]),
                          "r"(bfr[ni][0]), "r"(bfr[ni][1]));
        }
    }

    const int gm0 = bm * 128 + warp_m * 64 + (lane >> 2);
#pragma unroll
    for (int mi = 0; mi < 4; mi++) {
#pragma unroll
        for (int ni = 0; ni < 4; ni++) {
            int col = bn * 128 + warp_n * 32 + ni * 8 + (lane & 3) * 2;
            float b0 = __ldg(bias + col), b1 = __ldg(bias + col + 1);
            int r = gm0 + mi * 16;
            float2 v0 = make_float2(acc[mi][ni][0] + b0, acc[mi][ni][1] + b1);
            float2 v1 = make_float2(acc[mi][ni][2] + b0, acc[mi][ni][3] + b1);
            *(float2*)(C + (size_t)r * NDIM + col) = v0;
            *(float2*)(C + (size_t)(r + 8) * NDIM + col) = v1;
        }
    }
}

// ---------------------------------------------------------------------------
// launch
// ---------------------------------------------------------------------------
extern "C" void kernel_launch(void* const* d_in, const int* in_sizes, int n_in,
                              void* d_out, int out_size) {
    const float* hidden      = (const float*)d_in[0];
    const float* slot_w      = (const float*)d_in[1];
    const float* slot_b      = (const float*)d_in[2];
    const float* leaf_logits = (const float*)d_in[3];
    const float* node_params = (const float*)d_in[4];
    const float* out_w       = (const float*)d_in[5];
    const float* out_b       = (const float*)d_in[6];
    float* out = (float*)d_out;

    __half* slotsH; cudaGetSymbolAddress((void**)&slotsH, g_slotsH);
    u32*    selH;   cudaGetSymbolAddress((void**)&selH,   g_selH);
    __half* roots;  cudaGetSymbolAddress((void**)&roots,  g_roots);
    __half* outwT;  cudaGetSymbolAddress((void**)&outwT,  g_outwT);

    kA<<<NTOK / 8, 256>>>(hidden, slot_w, slot_b, slotsH);
    kB<<<(NW * 8) / 256, 256>>>(leaf_logits, selH);
    dim3 gt(NDIM / 32, NW / 32);
    kT<<<gt, dim3(32, 8)>>>(out_w, outwT);
    dim3 gc(NW / 32, NTOK / KC_TPB);   // 128 x 8 blocks
    kC<<<gc, 256>>>(node_params, selH, (const u32*)slotsH, roots);
    dim3 gd(NDIM / 128, NTOK / 128);
    kD<<<gd, 256>>>(roots, outwT, out_b, out);
}

// round 17
// speedup vs baseline: 1.5745x; 1.0155x over previous
#include <cuda.h>
#include <cuda_runtime.h>
#include <cuda_fp16.h>
#include <cstdint>

// ---------------------------------------------------------------------------
// Shapes: tokens T = 4096, D = 1024, W = 4096, SLOT = 8, depth 3
// ---------------------------------------------------------------------------
#define NTOK  4096
#define NDIM  1024
#define NW    4096
#define NSLOT 8

typedef unsigned long long u64;
typedef unsigned int u32;

// Scratch (device globals: allocation-free)
__device__ __align__(1024) __half g_slotsH[NTOK * 16];          // [tok][16] fp16 A-operand
__device__ __align__(1024) u32    g_selH[1024 * 4 * 32 * 2];    // B-fragment order, 1 MB
__device__ __align__(1024) __half g_roots[(size_t)NTOK * NW];   // 32 MB fp16
__device__ __align__(1024) __half g_outwT[(size_t)NDIM * NW];   // 8 MB fp16 [n][k]

// ---------------------------------------------------------------------------
// helpers
// ---------------------------------------------------------------------------
__device__ __forceinline__ float ftanh(float x) {
    x = fminf(fmaxf(x, -15.f), 15.f);
    float e = __expf(2.f * x);
    return __fdividef(e - 1.f, e + 1.f);
}
__device__ __forceinline__ uint32_t s2u(const void* p) {
    uint32_t a;
    asm("{ .reg .u64 t; cvta.to.shared.u64 t, %1; cvt.u32.u64 %0, t; }" : "=r"(a) : "l"(p));
    return a;
}

// packed f32x2 ops
__device__ __forceinline__ u64 pk(float lo, float hi) {
    u64 r; asm("mov.b64 %0,{%1,%2};" : "=l"(r) : "f"(lo), "f"(hi)); return r;
}
__device__ __forceinline__ u64 pk1(float x) { return pk(x, x); }
__device__ __forceinline__ void upk(u64 v, float& lo, float& hi) {
    asm("mov.b64 {%0,%1},%2;" : "=f"(lo), "=f"(hi) : "l"(v));
}
__device__ __forceinline__ u64 f2fma(u64 a, u64 b, u64 c) {
    u64 d; asm("fma.rn.f32x2 %0,%1,%2,%3;" : "=l"(d) : "l"(a), "l"(b), "l"(c)); return d;
}
__device__ __forceinline__ u64 f2mul(u64 a, u64 b) {
    u64 d; asm("mul.rn.f32x2 %0,%1,%2;" : "=l"(d) : "l"(a), "l"(b)); return d;
}
// tree node on packed token-pair, single-instruction tanh
__device__ __forceinline__ u64 node2t(u64 l, u64 r, u64 LW, u64 RW, u64 PW,
                                      u64 DWP, u64 DWN, u64 NB) {
    u64 a = f2fma(LW, l, NB);
    a = f2fma(RW, r, a);
    a = f2fma(PW, f2mul(l, r), a);
    a = f2fma(DWP, l, a);
    a = f2fma(DWN, r, a);
    float x0, x1; upk(a, x0, x1);
    float t0, t1;
    asm("tanh.approx.f32 %0,%1;" : "=f"(t0) : "f"(x0));
    asm("tanh.approx.f32 %0,%1;" : "=f"(t1) : "f"(x1));
    return pk(t0, t1);
}

// ---------------------------------------------------------------------------
// Kernel A: slots = tanh(hidden @ slot_w + slot_b) -> fp16 [tok][16]
//   cols 0..7 = slots, col 8 = 1.0 (bias lane), cols 9..15 = 0
// ---------------------------------------------------------------------------
__global__ __launch_bounds__(256) void kA(const float* __restrict__ hidden,
                                          const float* __restrict__ sw,
                                          const float* __restrict__ sb,
                                          __half* __restrict__ slotsH) {
    const int wid = threadIdx.x >> 5, lane = threadIdx.x & 31;
    const int token = blockIdx.x * 8 + wid;
    const float* h = hidden + (size_t)token * NDIM;

    float acc[8] = {0, 0, 0, 0, 0, 0, 0, 0};
    for (int d0 = 0; d0 < NDIM; d0 += 128) {
        float4 hv = *(const float4*)(h + d0 + lane * 4);
        const float* hp = (const float*)&hv;
#pragma unroll
        for (int j = 0; j < 4; j++) {
            const float4* wr = (const float4*)(sw + (size_t)(d0 + lane * 4 + j) * NSLOT);
            float4 w0 = wr[0], w1 = wr[1];
            float hj = hp[j];
            acc[0] = fmaf(hj, w0.x, acc[0]); acc[1] = fmaf(hj, w0.y, acc[1]);
            acc[2] = fmaf(hj, w0.z, acc[2]); acc[3] = fmaf(hj, w0.w, acc[3]);
            acc[4] = fmaf(hj, w1.x, acc[4]); acc[5] = fmaf(hj, w1.y, acc[5]);
            acc[6] = fmaf(hj, w1.z, acc[6]); acc[7] = fmaf(hj, w1.w, acc[7]);
        }
    }
#pragma unroll
    for (int k = 0; k < 8; k++) {
        float v = acc[k];
#pragma unroll
        for (int off = 16; off; off >>= 1) v += __shfl_xor_sync(0xFFFFFFFFu, v, off);
        if (lane == k) slotsH[token * 16 + k] = __float2half_rn(ftanh(v + sb[k]));
    }
    if (lane >= 8 && lane < 16)
        slotsH[token * 16 + lane] = __float2half_rn(lane == 8 ? 1.f : 0.f);
}

// ---------------------------------------------------------------------------
// Kernel B: softmax fold -> selector in mma B-fragment order (fp16)
// ---------------------------------------------------------------------------
__global__ __launch_bounds__(256) void kB(const float* __restrict__ logits,
                                          u32* __restrict__ selH) {
    const int idx = blockIdx.x * 256 + threadIdx.x;   // (w,l)
    const float* p = logits + (size_t)idx * 11;
    float x[11], mx = -1e30f;
#pragma unroll
    for (int c = 0; c < 11; c++) { x[c] = p[c]; mx = fmaxf(mx, x[c]); }
    float s = 0.f;
#pragma unroll
    for (int c = 0; c < 11; c++) { x[c] = __expf(x[c] - mx); s += x[c]; }
    const float inv = 1.0f / s;
    const int w = idx >> 3, l = idx & 7;
    const int u = w >> 2, wq = w & 3;
    const int c = l * 4 + wq, n = c >> 3, nc = c & 7;
    u32* base = selH + (size_t)(((u * 4 + n) * 32 + nc * 4) * 2);

#pragma unroll
    for (int i = 0; i < 4; i++) {
        u32 word;
        asm("cvt.rn.f16x2.f32 %0, %1, %2;" : "=r"(word)
            : "f"(x[2 * i + 1] * inv), "f"(x[2 * i] * inv));   // lo = x[2i]
        base[i * 2] = word;
    }
    u32 bw;
    asm("cvt.rn.f16x2.f32 %0, %1, %2;" : "=r"(bw)
        : "f"(0.f), "f"((x[10] - x[8]) * inv));                // lo = bias, hi = 0
    base[1] = bw;
    base[3] = 0; base[5] = 0; base[7] = 0;
}

// ---------------------------------------------------------------------------
// Kernel T: out_wT[n][k] = fp16(out_w[k][n])
// ---------------------------------------------------------------------------
__global__ __launch_bounds__(256) void kT(const float* __restrict__ w,
                                          __half* __restrict__ wt) {
    __shared__ float t[32][33];
    const int n0 = blockIdx.x * 32, k0 = blockIdx.y * 32;
#pragma unroll
    for (int j = 0; j < 4; j++)
        t[threadIdx.y + j * 8][threadIdx.x] =
            w[(size_t)(k0 + threadIdx.y + j * 8) * NDIM + n0 + threadIdx.x];
    __syncthreads();
#pragma unroll
    for (int j = 0; j < 4; j++)
        wt[(size_t)(n0 + threadIdx.y + j * 8) * NW + k0 + threadIdx.x] =
            __float2half_rn(t[threadIdx.x][threadIdx.y + j * 8]);
}

// ---------------------------------------------------------------------------
// Kernel C: leaf einsum on HMMA + register tree.
//   Block = 8 warps = 32 w, 512 tokens. Slots staged in smem (48B row pad,
//   conflict-free LDSM). Per 32-token pair: one barrier, double-buffered
//   32-row sroot tile, all-lane STS.32 stores, uint2 coalesced copy-out.
// ---------------------------------------------------------------------------
#define KC_TPB 512

__global__ __launch_bounds__(256) void kC(const float* __restrict__ np,
                                          const u32* __restrict__ selH,
                                          const u32* __restrict__ slotsH,
                                          __half* __restrict__ roots) {
    __shared__ __align__(16) char ssl[KC_TPB * 48];      // 24 KB slot tile
    __shared__ __align__(16) char sroot[2][32 * 72];     // double-buffered out tile
    const int tid = threadIdx.x, wid = tid >> 5, lane = tid & 31;
    const int u = blockIdx.x * 8 + wid;
    const int wblk = blockIdx.x * 32;
    const int t = lane & 3, q = lane >> 2;
    const int tok0 = blockIdx.y * KC_TPB;

    // stage slots: 1024 chunks of 16B, fully coalesced gmem reads
    const uint4* gsl = ((const uint4*)slotsH) + tok0 * 2;
    for (int c = tid; c < KC_TPB * 2; c += 256) {
        uint4 v = gsl[c];
        *(uint4*)(ssl + (c >> 1) * 48 + (c & 1) * 16) = v;
    }

    // loop-invariant B-fragments (selector)
    u32 bf[4][2];
#pragma unroll
    for (int n = 0; n < 4; n++) {
        const u32* p = selH + (size_t)(((u * 4 + n) * 32 + lane) * 2);
        bf[n][0] = p[0]; bf[n][1] = p[1];
    }
    const u64 LW = pk1(np[0]), RW = pk1(np[1]), PW = pk1(np[2]);
    const u64 DWP = pk1(np[3]), DWN = pk1(-np[3]), NB = pk1(np[4]);

    const int oc = t >> 1;
    const bool evenl = (t < 2);
    const int mat = lane >> 3, lrow = lane & 7;
    const uint32_t sbase = s2u(ssl) + ((mat & 1) * 8 + lrow) * 48 + (mat >> 1) * 16;
    // per-lane store slot within sroot row block
    const int srow_off = q + (t >> 1) * 8;            // row within 16-token tile
    const int scol = wid * 8 + (t & 1) * 4;           // byte col (w-pair)
    __syncthreads();

    for (int pair = 0; pair < KC_TPB / 32; pair++) {
        char* sr = sroot[pair & 1];
#pragma unroll
        for (int sub = 0; sub < 2; sub++) {
            const int tl = pair * 32 + sub * 16;
            u32 a0, a1, a2, a3;
            asm volatile(
                "ldmatrix.sync.aligned.m8n8.x4.shared.b16 {%0,%1,%2,%3}, [%4];"
                : "=r"(a0), "=r"(a1), "=r"(a2), "=r"(a3)
                : "r"(sbase + tl * 48));

            float z = 0.f;
            float acc[4][4];
#pragma unroll
            for (int n = 0; n < 4; n++)
                asm volatile(
                    "mma.sync.aligned.m16n8k16.row.col.f32.f16.f16.f32 "
                    "{%0,%1,%2,%3}, {%4,%5,%6,%7}, {%8,%9}, {%10,%10,%10,%10};"
                    : "=f"(acc[n][0]), "=f"(acc[n][1]), "=f"(acc[n][2]), "=f"(acc[n][3])
                    : "r"(a0), "r"(a1), "r"(a2), "r"(a3),
                      "r"(bf[n][0]), "r"(bf[n][1]), "f"(z));

            // keep own-wq column, exchange the other with partner lane (xor 2)
            u64 K[4], R[4];
#pragma unroll
            for (int n = 0; n < 4; n++) {
                K[n] = pk(acc[n][oc], acc[n][oc + 2]);
                u64 S = pk(acc[n][oc ^ 1], acc[n][(oc ^ 1) + 2]);
                R[n] = __shfl_xor_sync(0xFFFFFFFFu, S, 2);
            }
            u64 N1[4];
#pragma unroll
            for (int i = 0; i < 4; i++) {
                u64 E = evenl ? K[i] : R[i];
                u64 O = evenl ? R[i] : K[i];
                N1[i] = node2t(E, O, LW, RW, PW, DWP, DWN, NB);
            }
            u64 M0 = node2t(N1[0], N1[1], LW, RW, PW, DWP, DWN, NB);
            u64 M1 = node2t(N1[2], N1[3], LW, RW, PW, DWP, DWN, NB);
            u64 RT = node2t(M0, M1, LW, RW, PW, DWP, DWN, NB);

            float r0, r1; upk(RT, r0, r1);
            u32 val;   // lo = token q, hi = token q+8
            asm("cvt.rn.f16x2.f32 %0, %1, %2;" : "=r"(val) : "f"(r1), "f"(r0));

            // all-lane store: xor-2 partner holds adjacent-w value.
            // lanes t<2 emit token-q word (lo halves), t>=2 token-q+8 (hi halves)
            u32 pv = __shfl_xor_sync(0xFFFFFFFFu, val, 2);
            u32 word = (t < 2) ? __byte_perm(val, pv, 0x5410)
                               : __byte_perm(pv, val, 0x7632);
            *(u32*)(sr + (sub * 16 + srow_off) * 72 + scol) = word;
        }
        __syncthreads();
        // coalesced copy-out: 32 rows x 64B, uint2 per thread
        const int r = tid >> 3, cb = (tid & 7) * 8;
        uint2 v = *(const uint2*)(sr + r * 72 + cb);
        *(uint2*)((char*)(roots + (size_t)(tok0 + pair * 32 + r) * NW + wblk) + cb) = v;
    }
}

// ---------------------------------------------------------------------------
// Kernel D (unchanged): out = roots @ out_wT^T + out_b, fp16 HMMA m16n8k16
// ---------------------------------------------------------------------------
#define KD_ITERS (NW / 32)
#define KD_STAGE 16384

__device__ __forceinline__ void cpa16(uint32_t dst, const void* src) {
    asm volatile("cp.async.cg.shared.global [%0], [%1], 16;" :: "r"(dst), "l"(src) : "memory");
}

__global__ __launch_bounds__(256, 2) void kD(const __half* __restrict__ A,
                                             const __half* __restrict__ B,
                                             const float* __restrict__ bias,
                                             float* __restrict__ C) {
    __shared__ __align__(128) char smem[3 * KD_STAGE];
    const uint32_t sb = s2u(smem);
    const int tid = threadIdx.x, wid = tid >> 5, lane = tid & 31;
    const int bm = blockIdx.y, bn = blockIdx.x;
    const int warp_m = wid >> 2, warp_n = wid & 3;

    const int r0 = tid >> 2, c0 = tid & 3, r1 = r0 + 64;
    const uint32_t sA0 = r0 * 64 + ((c0 ^ ((r0 >> 1) & 3)) << 4);
    const uint32_t sA1 = r1 * 64 + ((c0 ^ ((r1 >> 1) & 3)) << 4);
    const __half* gA0 = A + (size_t)(bm * 128 + r0) * NW + c0 * 8;
    const __half* gA1 = A + (size_t)(bm * 128 + r1) * NW + c0 * 8;
    const __half* gB0 = B + (size_t)(bn * 128 + r0) * NW + c0 * 8;
    const __half* gB1 = B + (size_t)(bn * 128 + r1) * NW + c0 * 8;

    const int mat = lane >> 3, lrow = lane & 7;
    uint32_t adA[4][2], adB[2][2];
#pragma unroll
    for (int mi = 0; mi < 4; mi++) {
        int row = warp_m * 64 + mi * 16 + (mat & 1) * 8 + lrow;
        int coff = mat >> 1, sw = (row >> 1) & 3;
#pragma unroll
        for (int ks = 0; ks < 2; ks++)
            adA[mi][ks] = row * 64 + (((ks * 2 + coff) ^ sw) << 4);
    }
#pragma unroll
    for (int p = 0; p < 2; p++) {
        int nrow = warp_n * 32 + p * 16 + (mat >> 1) * 8 + lrow;
        int coff = mat & 1, sw = (nrow >> 1) & 3;
#pragma unroll
        for (int ks = 0; ks < 2; ks++)
            adB[p][ks] = 8192 + nrow * 64 + (((ks * 2 + coff) ^ sw) << 4);
    }

    float acc[4][4][4];
#pragma unroll
    for (int i = 0; i < 4; i++)
#pragma unroll
        for (int j = 0; j < 4; j++)
#pragma unroll
            for (int k = 0; k < 4; k++) acc[i][j][k] = 0.f;

#pragma unroll
    for (int s = 0; s < 2; s++) {
        uint32_t b = sb + s * KD_STAGE;
        cpa16(b + sA0, gA0 + s * 32);
        cpa16(b + sA1, gA1 + s * 32);
        cpa16(b + 8192 + sA0, gB0 + s * 32);
        cpa16(b + 8192 + sA1, gB1 + s * 32);
        asm volatile("cp.async.commit_group;" ::: "memory");
    }

    for (int k = 0; k < KD_ITERS; k++) {
        asm volatile("cp.async.wait_group 1;" ::: "memory");
        __syncthreads();
        const int s = k % 3;
        if (k + 2 < KD_ITERS) {
            const int sn = (k + 2) % 3;
            uint32_t b = sb + sn * KD_STAGE;
            cpa16(b + sA0, gA0 + (k + 2) * 32);
            cpa16(b + sA1, gA1 + (k + 2) * 32);
            cpa16(b + 8192 + sA0, gB0 + (k + 2) * 32);
            cpa16(b + 8192 + sA1, gB1 + (k + 2) * 32);
        }
        asm volatile("cp.async.commit_group;" ::: "memory");

        const uint32_t base = sb + s * KD_STAGE;
#pragma unroll
        for (int ks = 0; ks < 2; ks++) {
            uint32_t af[4][4], bfr[4][2];
#pragma unroll
            for (int mi = 0; mi < 4; mi++)
                asm volatile(
                    "ldmatrix.sync.aligned.m8n8.x4.shared.b16 {%0,%1,%2,%3}, [%4];"
                    : "=r"(af[mi][0]), "=r"(af[mi][1]), "=r"(af[mi][2]), "=r"(af[mi][3])
                    : "r"(base + adA[mi][ks]));
#pragma unroll
            for (int p = 0; p < 2; p++)
                asm volatile(
                    "ldmatrix.sync.aligned.m8n8.x4.shared.b16 {%0,%1,%2,%3}, [%4];"
                    : "=r"(bfr[2 * p][0]), "=r"(bfr[2 * p][1]),
                      "=r"(bfr[2 * p + 1][0]), "=r"(bfr[2 * p + 1][1])
                    : "r"(base + adB[p][ks]));
#pragma unroll
            for (int mi = 0; mi < 4; mi++)
#pragma unroll
                for (int ni = 0; ni < 4; ni++)
                    asm volatile(
                        "mma.sync.aligned.m16n8k16.row.col.f32.f16.f16.f32 "
                        "{%0,%1,%2,%3}, {%4,%5,%6,%7}, {%8,%9}, {%0,%1,%2,%3};"
                        : "+f"(acc[mi][ni][0]), "+f"(acc[mi][ni][1]),
                          "+f"(acc[mi][ni][2]), "+f"(acc[mi][ni][3])
                        : "r"(af[mi][0]), "r"(af[mi][1]), "r"(af[mi][2]), "r"(af[mi][3]),
                          "r"(bfr[ni][0]), "r"(bfr[ni][1]));
        }
    }

    const int gm0 = bm * 128 + warp_m * 64 + (lane >> 2);
#pragma unroll
    for (int mi = 0; mi < 4; mi++) {
#pragma unroll
        for (int ni = 0; ni < 4; ni++) {
            int col = bn * 128 + warp_n * 32 + ni * 8 + (lane & 3) * 2;
            float b0 = __ldg(bias + col), b1 = __ldg(bias + col + 1);
            int r = gm0 + mi * 16;
            float2 v0 = make_float2(acc[mi][ni][0] + b0, acc[mi][ni][1] + b1);
            float2 v1 = make_float2(acc[mi][ni][2] + b0, acc[mi][ni][3] + b1);
            *(float2*)(C + (size_t)r * NDIM + col) = v0;
            *(float2*)(C + (size_t)(r + 8) * NDIM + col) = v1;
        }
    }
}

// ---------------------------------------------------------------------------
// launch
// ---------------------------------------------------------------------------
extern "C" void kernel_launch(void* const* d_in, const int* in_sizes, int n_in,
                              void* d_out, int out_size) {
    const float* hidden      = (const float*)d_in[0];
    const float* slot_w      = (const float*)d_in[1];
    const float* slot_b      = (const float*)d_in[2];
    const float* leaf_logits = (const float*)d_in[3];
    const float* node_params = (const float*)d_in[4];
    const float* out_w       = (const float*)d_in[5];
    const float* out_b       = (const float*)d_in[6];
    float* out = (float*)d_out;

    __half* slotsH; cudaGetSymbolAddress((void**)&slotsH, g_slotsH);
    u32*    selH;   cudaGetSymbolAddress((void**)&selH,   g_selH);
    __half* roots;  cudaGetSymbolAddress((void**)&roots,  g_roots);
    __half* outwT;  cudaGetSymbolAddress((void**)&outwT,  g_outwT);

    kA<<<NTOK / 8, 256>>>(hidden, slot_w, slot_b, slotsH);
    kB<<<(NW * 8) / 256, 256>>>(leaf_logits, selH);
    dim3 gt(NDIM / 32, NW / 32);
    kT<<<gt, dim3(32, 8)>>>(out_w, outwT);
    dim3 gc(NW / 32, NTOK / KC_TPB);   // 128 x 8 blocks
    kC<<<gc, 256>>>(node_params, selH, (const u32*)slotsH, roots);
    dim3 gd(NDIM / 128, NTOK / 128);
    kD<<<gd, 256>>>(roots, outwT, out_b, out);
}